// round 1
// baseline (speedup 1.0000x reference)
#include <cuda_runtime.h>
#include <cuda_bf16.h>

// GridSpatialIntegral: input [B=64, C=2, WY=512, WX=512] fp32.
//   out[:,0,:,:] = cumsum over x of in[:,0,:,:]
//   out[:,1,:,:] = cumsum over y of in[:,1,:,:]
//
// Single fused kernel:
//   blocks [0, 128)        : channel-1 column scans (serial over y, coalesced in x)
//   blocks [128, 128+4096) : channel-0 row scans (warp per row)

#define B   64
#define WY  512
#define WX  512

#define CH1_BLOCKS 128                 // 64 batches * 2 x-tiles of 256 columns
#define CH0_BLOCKS 4096                // 64*512 rows / 8 warps-per-block
#define TOTAL_BLOCKS (CH1_BLOCKS + CH0_BLOCKS)
#define THREADS 256

__global__ __launch_bounds__(THREADS)
void grid_spatial_integral_kernel(const float* __restrict__ in,
                                  float* __restrict__ out) {
    const int bx = blockIdx.x;

    if (bx < CH1_BLOCKS) {
        // ---------------- Channel 1: cumsum along y ----------------
        // block -> (batch, x-tile). thread -> one column x.
        const int b  = bx >> 1;
        const int x  = ((bx & 1) << 8) + threadIdx.x;   // 0..511

        const int base = ((b * 2 + 1) * WY) * WX + x;   // row 0 of channel 1
        const float* __restrict__ p = in  + base;
        float*       __restrict__ q = out + base;

        float acc = 0.0f;
        #pragma unroll 1
        for (int y0 = 0; y0 < WY; y0 += 16) {
            float v[16];
            #pragma unroll
            for (int k = 0; k < 16; ++k)
                v[k] = p[(y0 + k) * WX];
            #pragma unroll
            for (int k = 0; k < 16; ++k) {
                acc += v[k];
                q[(y0 + k) * WX] = acc;
            }
        }
    } else {
        // ---------------- Channel 0: cumsum along x ----------------
        // warp per 512-float row. lane owns 16 contiguous floats.
        const int idx  = bx - CH1_BLOCKS;               // 0..4095
        const int wid  = threadIdx.x >> 5;              // 0..7
        const int lane = threadIdx.x & 31;
        const int row  = idx * 8 + wid;                 // 0..32767
        const int b    = row >> 9;                      // row / 512
        const int y    = row & 511;

        const int base = ((b * 2 + 0) * WY + y) * WX;   // row start, channel 0
        const float4* __restrict__ src = (const float4*)(in  + base);
        float4*       __restrict__ dst = (float4*)(out + base);

        float4 a0 = src[lane * 4 + 0];
        float4 a1 = src[lane * 4 + 1];
        float4 a2 = src[lane * 4 + 2];
        float4 a3 = src[lane * 4 + 3];

        // serial inclusive scan over this lane's 16 elements
        a0.y += a0.x; a0.z += a0.y; a0.w += a0.z;
        a1.x += a0.w; a1.y += a1.x; a1.z += a1.y; a1.w += a1.z;
        a2.x += a1.w; a2.y += a2.x; a2.z += a2.y; a2.w += a2.z;
        a3.x += a2.w; a3.y += a3.x; a3.z += a3.y; a3.w += a3.z;

        // exclusive warp scan of lane totals
        const float tot = a3.w;
        float pre = tot;
        #pragma unroll
        for (int d = 1; d < 32; d <<= 1) {
            float n = __shfl_up_sync(0xffffffffu, pre, d);
            if (lane >= d) pre += n;
        }
        pre -= tot;   // exclusive prefix of totals

        a0.x += pre; a0.y += pre; a0.z += pre; a0.w += pre;
        a1.x += pre; a1.y += pre; a1.z += pre; a1.w += pre;
        a2.x += pre; a2.y += pre; a2.z += pre; a2.w += pre;
        a3.x += pre; a3.y += pre; a3.z += pre; a3.w += pre;

        dst[lane * 4 + 0] = a0;
        dst[lane * 4 + 1] = a1;
        dst[lane * 4 + 2] = a2;
        dst[lane * 4 + 3] = a3;
    }
}

extern "C" void kernel_launch(void* const* d_in, const int* in_sizes, int n_in,
                              void* d_out, int out_size) {
    const float* in  = (const float*)d_in[0];
    float*       out = (float*)d_out;
    grid_spatial_integral_kernel<<<TOTAL_BLOCKS, THREADS>>>(in, out);
}

// round 2
// speedup vs baseline: 1.1122x; 1.1122x over previous
#include <cuda_runtime.h>
#include <cuda_bf16.h>

// GridSpatialIntegral: input [B=64, C=2, WY=512, WX=512] fp32.
//   out[:,0,:,:] = cumsum over x of in[:,0,:,:]
//   out[:,1,:,:] = cumsum over y of in[:,1,:,:]
//
// Single fused kernel:
//   blocks [0, 128)        : channel-1 column scans (serial over y, coalesced
//                            in x, double-buffered 16-deep load pipeline)
//   blocks [128, 128+4096) : channel-0 row scans (warp per row)

#define B   64
#define WY  512
#define WX  512

#define CH1_BLOCKS 128                 // 64 batches * 2 x-tiles of 256 columns
#define CH0_BLOCKS 4096                // 64*512 rows / 8 warps-per-block
#define TOTAL_BLOCKS (CH1_BLOCKS + CH0_BLOCKS)
#define THREADS 256

__global__ __launch_bounds__(THREADS)
void grid_spatial_integral_kernel(const float* __restrict__ in,
                                  float* __restrict__ out) {
    const int bx = blockIdx.x;

    if (bx < CH1_BLOCKS) {
        // ---------------- Channel 1: cumsum along y ----------------
        // block -> (batch, x-tile). thread -> one column x.
        // Double-buffered: loads for batch i+1 are issued before the
        // accumulate+store chain of batch i, keeping ~32 loads in flight
        // per thread at steady state.
        const int b  = bx >> 1;
        const int x  = ((bx & 1) << 8) + threadIdx.x;   // 0..511

        const int base = ((b * 2 + 1) * WY) * WX + x;   // row 0 of channel 1
        const float* __restrict__ p = in  + base;
        float*       __restrict__ q = out + base;

        float buf0[16], buf1[16];

        #pragma unroll
        for (int k = 0; k < 16; ++k)
            buf0[k] = __ldcs(p + k * WX);

        float acc = 0.0f;

        #pragma unroll 1
        for (int y0 = 0; y0 < WY; y0 += 32) {
            // prefetch batch at y0+16
            #pragma unroll
            for (int k = 0; k < 16; ++k)
                buf1[k] = __ldcs(p + (y0 + 16 + k) * WX);

            // consume batch at y0
            #pragma unroll
            for (int k = 0; k < 16; ++k) {
                acc += buf0[k];
                __stcs(q + (y0 + k) * WX, acc);
            }

            // prefetch batch at y0+32 (skipped on last iteration)
            if (y0 + 32 < WY) {
                #pragma unroll
                for (int k = 0; k < 16; ++k)
                    buf0[k] = __ldcs(p + (y0 + 32 + k) * WX);
            }

            // consume batch at y0+16
            #pragma unroll
            for (int k = 0; k < 16; ++k) {
                acc += buf1[k];
                __stcs(q + (y0 + 16 + k) * WX, acc);
            }
        }
    } else {
        // ---------------- Channel 0: cumsum along x ----------------
        // warp per 512-float row. lane owns 16 contiguous floats.
        const int idx  = bx - CH1_BLOCKS;               // 0..4095
        const int wid  = threadIdx.x >> 5;              // 0..7
        const int lane = threadIdx.x & 31;
        const int row  = idx * 8 + wid;                 // 0..32767
        const int b    = row >> 9;                      // row / 512
        const int y    = row & 511;

        const int base = ((b * 2 + 0) * WY + y) * WX;   // row start, channel 0
        const float4* __restrict__ src = (const float4*)(in  + base);
        float4*       __restrict__ dst = (float4*)(out + base);

        float4 a0 = __ldcs(src + lane * 4 + 0);
        float4 a1 = __ldcs(src + lane * 4 + 1);
        float4 a2 = __ldcs(src + lane * 4 + 2);
        float4 a3 = __ldcs(src + lane * 4 + 3);

        // serial inclusive scan over this lane's 16 elements
        a0.y += a0.x; a0.z += a0.y; a0.w += a0.z;
        a1.x += a0.w; a1.y += a1.x; a1.z += a1.y; a1.w += a1.z;
        a2.x += a1.w; a2.y += a2.x; a2.z += a2.y; a2.w += a2.z;
        a3.x += a2.w; a3.y += a3.x; a3.z += a3.y; a3.w += a3.z;

        // exclusive warp scan of lane totals
        const float tot = a3.w;
        float pre = tot;
        #pragma unroll
        for (int d = 1; d < 32; d <<= 1) {
            float n = __shfl_up_sync(0xffffffffu, pre, d);
            if (lane >= d) pre += n;
        }
        pre -= tot;   // exclusive prefix of totals

        a0.x += pre; a0.y += pre; a0.z += pre; a0.w += pre;
        a1.x += pre; a1.y += pre; a1.z += pre; a1.w += pre;
        a2.x += pre; a2.y += pre; a2.z += pre; a2.w += pre;
        a3.x += pre; a3.y += pre; a3.z += pre; a3.w += pre;

        __stcs(dst + lane * 4 + 0, a0);
        __stcs(dst + lane * 4 + 1, a1);
        __stcs(dst + lane * 4 + 2, a2);
        __stcs(dst + lane * 4 + 3, a3);
    }
}

extern "C" void kernel_launch(void* const* d_in, const int* in_sizes, int n_in,
                              void* d_out, int out_size) {
    const float* in  = (const float*)d_in[0];
    float*       out = (float*)d_out;
    grid_spatial_integral_kernel<<<TOTAL_BLOCKS, THREADS>>>(in, out);
}

// round 3
// speedup vs baseline: 1.1280x; 1.0142x over previous
#include <cuda_runtime.h>
#include <cuda_bf16.h>

// GridSpatialIntegral: input [B=64, C=2, WY=512, WX=512] fp32.
//   out[:,0,:,:] = cumsum over x of in[:,0,:,:]
//   out[:,1,:,:] = cumsum over y of in[:,1,:,:]
//
// Single fused kernel:
//   blocks [0, 128)        : channel-1 column scans, 4-buffer rotation with
//                            prefetch distance 3 (~48-64 rows of reads in
//                            flight per thread) to beat the BW*latency product
//   blocks [128, 128+4096) : channel-0 row scans (warp per row)

#define B   64
#define WY  512
#define WX  512

#define CH1_BLOCKS 128                 // 64 batches * 2 x-tiles of 256 columns
#define CH0_BLOCKS 4096                // 64*512 rows / 8 warps-per-block
#define TOTAL_BLOCKS (CH1_BLOCKS + CH0_BLOCKS)
#define THREADS 256

#define LOAD_BATCH(buf, y0)                                   \
    {                                                         \
        _Pragma("unroll")                                     \
        for (int k = 0; k < 16; ++k)                          \
            buf[k] = __ldcs(p + ((y0) + k) * WX);             \
    }

#define CONSUME_BATCH(buf, y0)                                \
    {                                                         \
        _Pragma("unroll")                                     \
        for (int k = 0; k < 16; ++k) {                        \
            acc += buf[k];                                    \
            __stcs(q + ((y0) + k) * WX, acc);                 \
        }                                                     \
    }

__global__ __launch_bounds__(THREADS)
void grid_spatial_integral_kernel(const float* __restrict__ in,
                                  float* __restrict__ out) {
    const int bx = blockIdx.x;

    if (bx < CH1_BLOCKS) {
        // ---------------- Channel 1: cumsum along y ----------------
        // block -> (batch, x-tile). thread -> one column x.
        const int b  = bx >> 1;
        const int x  = ((bx & 1) << 8) + threadIdx.x;   // 0..511

        const int base = ((b * 2 + 1) * WY) * WX + x;   // row 0 of channel 1
        const float* __restrict__ p = in  + base;
        float*       __restrict__ q = out + base;

        // 4 rotating buffers of 16 rows each; prefetch distance 3.
        float v0[16], v1[16], v2[16], v3[16];

        LOAD_BATCH(v0, 0);
        LOAD_BATCH(v1, 16);
        LOAD_BATCH(v2, 32);

        float acc = 0.0f;

        // 32 batches of 16 rows, processed 4 per outer iteration so buffer
        // indices stay compile-time.
        #pragma unroll 1
        for (int j = 0; j < 8; ++j) {
            const int y = j * 64;

            if (y + 48 < WY) LOAD_BATCH(v3, y + 48);
            CONSUME_BATCH(v0, y);

            if (y + 64 < WY) LOAD_BATCH(v0, y + 64);
            CONSUME_BATCH(v1, y + 16);

            if (y + 80 < WY) LOAD_BATCH(v1, y + 80);
            CONSUME_BATCH(v2, y + 32);

            if (y + 96 < WY) LOAD_BATCH(v2, y + 96);
            CONSUME_BATCH(v3, y + 48);
        }
    } else {
        // ---------------- Channel 0: cumsum along x ----------------
        // warp per 512-float row. lane owns 16 contiguous floats.
        const int idx  = bx - CH1_BLOCKS;               // 0..4095
        const int wid  = threadIdx.x >> 5;              // 0..7
        const int lane = threadIdx.x & 31;
        const int row  = idx * 8 + wid;                 // 0..32767
        const int b    = row >> 9;                      // row / 512
        const int y    = row & 511;

        const int base = ((b * 2 + 0) * WY + y) * WX;   // row start, channel 0
        const float4* __restrict__ src = (const float4*)(in  + base);
        float4*       __restrict__ dst = (float4*)(out + base);

        float4 a0 = __ldcs(src + lane * 4 + 0);
        float4 a1 = __ldcs(src + lane * 4 + 1);
        float4 a2 = __ldcs(src + lane * 4 + 2);
        float4 a3 = __ldcs(src + lane * 4 + 3);

        // serial inclusive scan over this lane's 16 elements
        a0.y += a0.x; a0.z += a0.y; a0.w += a0.z;
        a1.x += a0.w; a1.y += a1.x; a1.z += a1.y; a1.w += a1.z;
        a2.x += a1.w; a2.y += a2.x; a2.z += a2.y; a2.w += a2.z;
        a3.x += a2.w; a3.y += a3.x; a3.z += a3.y; a3.w += a3.z;

        // exclusive warp scan of lane totals
        const float tot = a3.w;
        float pre = tot;
        #pragma unroll
        for (int d = 1; d < 32; d <<= 1) {
            float n = __shfl_up_sync(0xffffffffu, pre, d);
            if (lane >= d) pre += n;
        }
        pre -= tot;   // exclusive prefix of totals

        a0.x += pre; a0.y += pre; a0.z += pre; a0.w += pre;
        a1.x += pre; a1.y += pre; a1.z += pre; a1.w += pre;
        a2.x += pre; a2.y += pre; a2.z += pre; a2.w += pre;
        a3.x += pre; a3.y += pre; a3.z += pre; a3.w += pre;

        __stcs(dst + lane * 4 + 0, a0);
        __stcs(dst + lane * 4 + 1, a1);
        __stcs(dst + lane * 4 + 2, a2);
        __stcs(dst + lane * 4 + 3, a3);
    }
}

extern "C" void kernel_launch(void* const* d_in, const int* in_sizes, int n_in,
                              void* d_out, int out_size) {
    const float* in  = (const float*)d_in[0];
    float*       out = (float*)d_out;
    grid_spatial_integral_kernel<<<TOTAL_BLOCKS, THREADS>>>(in, out);
}

// round 4
// speedup vs baseline: 1.2536x; 1.1114x over previous
#include <cuda_runtime.h>
#include <cuda_bf16.h>

// GridSpatialIntegral: input [B=64, C=2, WY=512, WX=512] fp32.
//   out[:,0,:,:] = cumsum over x of in[:,0,:,:]
//   out[:,1,:,:] = cumsum over y of in[:,1,:,:]
//
// Single fused kernel:
//   blocks [0, 1024)       : channel-1. Block owns 32 columns x 512 rows.
//                            warp w owns 64-row segment w; segment totals are
//                            exchanged through smem (no inter-block sync).
//   blocks [1024, 1024+4096): channel-0 row scans (warp per row),
//                            lane-contiguous loads (nL=4 per LDG.128).

#define B   64
#define WY  512
#define WX  512

#define CH1_BLOCKS 1024                // 32768 columns / 32 per block
#define CH0_BLOCKS 4096                // 32768 rows / 8 warps-per-block
#define TOTAL_BLOCKS (CH1_BLOCKS + CH0_BLOCKS)
#define THREADS 256

__device__ __forceinline__ float warp_incl_scan(float v, int lane) {
    #pragma unroll
    for (int d = 1; d < 32; d <<= 1) {
        float n = __shfl_up_sync(0xffffffffu, v, d);
        if (lane >= d) v += n;
    }
    return v;
}

__global__ __launch_bounds__(THREADS)
void grid_spatial_integral_kernel(const float* __restrict__ in,
                                  float* __restrict__ out) {
    const int bx = blockIdx.x;
    __shared__ float seg_totals[8][32];

    if (bx < CH1_BLOCKS) {
        // ---------------- Channel 1: cumsum along y ----------------
        // block -> (batch, 32-column group). warp -> 64-row segment.
        const int lane = threadIdx.x & 31;
        const int seg  = threadIdx.x >> 5;          // 0..7
        const int b    = bx >> 4;                   // 16 col-groups per batch
        const int xg   = bx & 15;
        const int x    = xg * 32 + lane;            // 0..511

        const int base = ((b * 2 + 1) * WY + seg * 64) * WX + x;
        const float* __restrict__ p = in  + base;
        float*       __restrict__ q = out + base;

        // load 64 rows into registers (coalesced 128B per warp instruction)
        float v[64];
        #pragma unroll
        for (int k = 0; k < 64; ++k)
            v[k] = __ldcs(p + k * WX);

        // in-register inclusive prefix over this segment
        #pragma unroll
        for (int k = 1; k < 64; ++k)
            v[k] += v[k - 1];

        // publish segment total, gather carry from lower segments
        seg_totals[seg][lane] = v[63];
        __syncthreads();

        float carry = 0.0f;
        #pragma unroll
        for (int s = 0; s < 7; ++s)
            if (s < seg) carry += seg_totals[s][lane];

        #pragma unroll
        for (int k = 0; k < 64; ++k)
            __stcs(q + k * WX, v[k] + carry);
    } else {
        // ---------------- Channel 0: cumsum along x ----------------
        // warp per 512-float row. lane-contiguous float4 loads:
        // chunk id c = i*32 + lane holds elements [4c, 4c+4).
        const int idx  = bx - CH1_BLOCKS;           // 0..4095
        const int wid  = threadIdx.x >> 5;          // 0..7
        const int lane = threadIdx.x & 31;
        const int row  = idx * 8 + wid;             // 0..32767
        const int b    = row >> 9;
        const int y    = row & 511;

        const int base = ((b * 2 + 0) * WY + y) * WX;
        const float4* __restrict__ src = (const float4*)(in  + base);
        float4*       __restrict__ dst = (float4*)(out + base);

        float4 a0 = __ldcs(src + 0 * 32 + lane);
        float4 a1 = __ldcs(src + 1 * 32 + lane);
        float4 a2 = __ldcs(src + 2 * 32 + lane);
        float4 a3 = __ldcs(src + 3 * 32 + lane);

        // inclusive scan inside each 4-element chunk
        a0.y += a0.x; a0.z += a0.y; a0.w += a0.z;
        a1.y += a1.x; a1.z += a1.y; a1.w += a1.z;
        a2.y += a2.x; a2.z += a2.y; a2.w += a2.z;
        a3.y += a3.x; a3.z += a3.y; a3.w += a3.z;

        // warp scans of chunk totals, one per chunk-row i
        const float t0 = a0.w, t1 = a1.w, t2 = a2.w, t3 = a3.w;
        float i0 = warp_incl_scan(t0, lane);
        float i1 = warp_incl_scan(t1, lane);
        float i2 = warp_incl_scan(t2, lane);
        float i3 = warp_incl_scan(t3, lane);
        const float T0 = __shfl_sync(0xffffffffu, i0, 31);
        const float T1 = __shfl_sync(0xffffffffu, i1, 31);
        const float T2 = __shfl_sync(0xffffffffu, i2, 31);

        // offset for chunk (i, lane) = sum_{j<i} T_j + excl_i(lane)
        const float o0 = i0 - t0;
        const float o1 = (i1 - t1) + T0;
        const float o2 = (i2 - t2) + T0 + T1;
        const float o3 = (i3 - t3) + T0 + T1 + T2;

        a0.x += o0; a0.y += o0; a0.z += o0; a0.w += o0;
        a1.x += o1; a1.y += o1; a1.z += o1; a1.w += o1;
        a2.x += o2; a2.y += o2; a2.z += o2; a2.w += o2;
        a3.x += o3; a3.y += o3; a3.z += o3; a3.w += o3;

        __stcs(dst + 0 * 32 + lane, a0);
        __stcs(dst + 1 * 32 + lane, a1);
        __stcs(dst + 2 * 32 + lane, a2);
        __stcs(dst + 3 * 32 + lane, a3);
    }
}

extern "C" void kernel_launch(void* const* d_in, const int* in_sizes, int n_in,
                              void* d_out, int out_size) {
    const float* in  = (const float*)d_in[0];
    float*       out = (float*)d_out;
    grid_spatial_integral_kernel<<<TOTAL_BLOCKS, THREADS>>>(in, out);
}

// round 5
// speedup vs baseline: 1.2831x; 1.0235x over previous
#include <cuda_runtime.h>
#include <cuda_bf16.h>

// GridSpatialIntegral: input [B=64, C=2, WY=512, WX=512] fp32.
//   out[:,0,:,:] = cumsum over x of in[:,0,:,:]
//   out[:,1,:,:] = cumsum over y of in[:,1,:,:]
//
// Single fused kernel, 512-thread blocks:
//   blocks [0, 1024)        : channel-1. Block owns 32 columns x 512 rows.
//                             16 warps; warp w owns 32-row segment w; segment
//                             totals exchanged through smem.
//   blocks [1024, 1024+2048): channel-0 row scans (warp per row, 16 rows/blk),
//                             lane-contiguous float4 loads.

#define B   64
#define WY  512
#define WX  512

#define CH1_BLOCKS 1024                // 32768 columns / 32 per block
#define CH0_BLOCKS 2048                // 32768 rows / 16 warps-per-block
#define TOTAL_BLOCKS (CH1_BLOCKS + CH0_BLOCKS)
#define THREADS 512

__device__ __forceinline__ float warp_incl_scan(float v, int lane) {
    #pragma unroll
    for (int d = 1; d < 32; d <<= 1) {
        float n = __shfl_up_sync(0xffffffffu, v, d);
        if (lane >= d) v += n;
    }
    return v;
}

__global__ __launch_bounds__(THREADS, 2)
void grid_spatial_integral_kernel(const float* __restrict__ in,
                                  float* __restrict__ out) {
    const int bx = blockIdx.x;
    __shared__ float seg_totals[16][32];

    if (bx < CH1_BLOCKS) {
        // ---------------- Channel 1: cumsum along y ----------------
        // block -> (batch, 32-column group). warp -> 32-row segment.
        const int lane = threadIdx.x & 31;
        const int seg  = threadIdx.x >> 5;          // 0..15
        const int b    = bx >> 4;                   // 16 col-groups per batch
        const int xg   = bx & 15;
        const int x    = xg * 32 + lane;            // 0..511

        const int base = ((b * 2 + 1) * WY + seg * 32) * WX + x;
        const float* __restrict__ p = in  + base;
        float*       __restrict__ q = out + base;

        // load 32 rows into registers (coalesced 128B per warp instruction)
        float v[32];
        #pragma unroll
        for (int k = 0; k < 32; ++k)
            v[k] = __ldcs(p + k * WX);

        // in-register inclusive prefix over this segment
        #pragma unroll
        for (int k = 1; k < 32; ++k)
            v[k] += v[k - 1];

        // publish segment total, gather carry from lower segments
        seg_totals[seg][lane] = v[31];
        __syncthreads();

        float carry = 0.0f;
        #pragma unroll
        for (int s = 0; s < 15; ++s)
            if (s < seg) carry += seg_totals[s][lane];

        #pragma unroll
        for (int k = 0; k < 32; ++k)
            __stcs(q + k * WX, v[k] + carry);
    } else {
        // ---------------- Channel 0: cumsum along x ----------------
        // warp per 512-float row. lane-contiguous float4 loads:
        // chunk id c = i*32 + lane holds elements [4c, 4c+4).
        const int idx  = bx - CH1_BLOCKS;           // 0..2047
        const int wid  = threadIdx.x >> 5;          // 0..15
        const int lane = threadIdx.x & 31;
        const int row  = idx * 16 + wid;            // 0..32767
        const int b    = row >> 9;
        const int y    = row & 511;

        const int base = ((b * 2 + 0) * WY + y) * WX;
        const float4* __restrict__ src = (const float4*)(in  + base);
        float4*       __restrict__ dst = (float4*)(out + base);

        float4 a0 = __ldcs(src + 0 * 32 + lane);
        float4 a1 = __ldcs(src + 1 * 32 + lane);
        float4 a2 = __ldcs(src + 2 * 32 + lane);
        float4 a3 = __ldcs(src + 3 * 32 + lane);

        // inclusive scan inside each 4-element chunk
        a0.y += a0.x; a0.z += a0.y; a0.w += a0.z;
        a1.y += a1.x; a1.z += a1.y; a1.w += a1.z;
        a2.y += a2.x; a2.z += a2.y; a2.w += a2.z;
        a3.y += a3.x; a3.z += a3.y; a3.w += a3.z;

        // warp scans of chunk totals, one per chunk-row i
        const float t0 = a0.w, t1 = a1.w, t2 = a2.w, t3 = a3.w;
        float i0 = warp_incl_scan(t0, lane);
        float i1 = warp_incl_scan(t1, lane);
        float i2 = warp_incl_scan(t2, lane);
        float i3 = warp_incl_scan(t3, lane);
        const float T0 = __shfl_sync(0xffffffffu, i0, 31);
        const float T1 = __shfl_sync(0xffffffffu, i1, 31);
        const float T2 = __shfl_sync(0xffffffffu, i2, 31);

        // offset for chunk (i, lane) = sum_{j<i} T_j + excl_i(lane)
        const float o0 = i0 - t0;
        const float o1 = (i1 - t1) + T0;
        const float o2 = (i2 - t2) + T0 + T1;
        const float o3 = (i3 - t3) + T0 + T1 + T2;

        a0.x += o0; a0.y += o0; a0.z += o0; a0.w += o0;
        a1.x += o1; a1.y += o1; a1.z += o1; a1.w += o1;
        a2.x += o2; a2.y += o2; a2.z += o2; a2.w += o2;
        a3.x += o3; a3.y += o3; a3.z += o3; a3.w += o3;

        __stcs(dst + 0 * 32 + lane, a0);
        __stcs(dst + 1 * 32 + lane, a1);
        __stcs(dst + 2 * 32 + lane, a2);
        __stcs(dst + 3 * 32 + lane, a3);
    }
}

extern "C" void kernel_launch(void* const* d_in, const int* in_sizes, int n_in,
                              void* d_out, int out_size) {
    const float* in  = (const float*)d_in[0];
    float*       out = (float*)d_out;
    grid_spatial_integral_kernel<<<TOTAL_BLOCKS, THREADS>>>(in, out);
}